// round 17
// baseline (speedup 1.0000x reference)
#include <cuda_runtime.h>
#include <cuda_fp16.h>
#include <cstdint>

// ---------------------------------------------------------------------------
// RGCN gather-MM:  out[dst[e]] += feat[src[e]] @ W[etype[e]]
//   E = 1,000,000 edges, N = 100,000 nodes, D_in = D_out = 64, R = 16
//
// Pipeline (4 launches):
//   1. k_prep    : zero(out) + W^T fp16 prep + feat fp16 convert
//                  + per-block relation histogram
//   2. k_scan    : parallel column scan -> PADDED rel bases (TILE-aligned),
//                  tile->rel table, pad slots filled with (0,-1)
//   3. k_scatter : warp-aggregated counting-sort of packed (src,dst) int2
//   4. k_rgcn_mma: persistent grouped GEMM, 128-edge tiles (tile t =
//        g_edge[128t..]), 4 warps/CTA, 5 CTAs/SM, XOR-swizzled dense A
//        stages, 2-stage cp.async pipeline, row-cooperative gather,
//        single-pass fp16 MMA. Epilogue: shfl_xor -> red.global.add.v4.f32.
// ---------------------------------------------------------------------------

#define E_MAX    1000000
#define N_NODES  100000
#define NB_SORT  1024
#define TILE     128
#define BLK      128
#define MAXT     7828       // ceil(E/128) + 15
#define GRID_MMA 760        // 5 CTAs x 152 SMs, persistent

// ---- static device scratch (allocation is forbidden) ----
__device__ int2 g_edge[E_MAX + 16 * TILE];        // padded, rel-sorted
__device__ int g_blockcounts[NB_SORT * 16];
__device__ int g_relofs[17];                      // PADDED bases (x TILE)
__device__ int g_tile_rel[MAXT];
__device__ unsigned short g_Bh[16 * 4096];        // fp16 W^T, [r][n][k]
__device__ unsigned short g_fh[N_NODES * 64];     // feat fp16

// ---------------------------------------------------------------------------
// fused: zero out + prep W + convert feat + per-block relation histogram
__global__ void k_prep(float4* out, int n4, const float* __restrict__ W,
                       const float* __restrict__ feat,
                       const int* __restrict__ et, int E, int chunk) {
    int gtid = blockIdx.x * blockDim.x + threadIdx.x;
    int gstr = gridDim.x * blockDim.x;

    for (int i = gtid; i < n4; i += gstr)
        out[i] = make_float4(0.f, 0.f, 0.f, 0.f);

    // feat [N,64] fp32 -> g_fh fp16 (one float4 -> 4 halves)
    const float4* fv = (const float4*)feat;
    for (int i = gtid; i < N_NODES * 16; i += gstr) {
        float4 v = fv[i];
        uint2 hp = make_uint2(
            (unsigned)__half_as_ushort(__float2half_rn(v.x)) |
            ((unsigned)__half_as_ushort(__float2half_rn(v.y)) << 16),
            (unsigned)__half_as_ushort(__float2half_rn(v.z)) |
            ((unsigned)__half_as_ushort(__float2half_rn(v.w)) << 16));
        ((uint2*)g_fh)[i] = hp;
    }

    // W[r] is [k][n] row-major fp32 -> g_Bh[r][n][k] fp16
    if (blockIdx.x < 16) {
        int r = blockIdx.x;
        for (int idx = threadIdx.x; idx < 4096; idx += blockDim.x) {
            int n = idx >> 6, k = idx & 63;
            g_Bh[r * 4096 + idx] =
                __half_as_ushort(__float2half_rn(W[r * 4096 + k * 64 + n]));
        }
    }

    __shared__ int cnt[16];
    if (threadIdx.x < 16) cnt[threadIdx.x] = 0;
    __syncthreads();
    int lo = blockIdx.x * chunk, hi = min(E, lo + chunk);
    for (int e = lo + threadIdx.x; e < hi; e += blockDim.x)
        atomicAdd(&cnt[et[e]], 1);
    __syncthreads();
    if (threadIdx.x < 16)
        g_blockcounts[blockIdx.x * 16 + threadIdx.x] = cnt[threadIdx.x];
}

// ---------------------------------------------------------------------------
// single block, 512 threads. warp w owns column w; lane l owns a 32-block
// register-resident chunk. Produces PADDED rel bases, tile table, pad fill.
__global__ void k_scan(void) {
    __shared__ int rel_total[16];
    __shared__ int tileofs_s[17];
    int w = threadIdx.x >> 5, lane = threadIdx.x & 31;

    int vals[32];
    #pragma unroll
    for (int i = 0; i < 32; i++)
        vals[i] = g_blockcounts[(lane * 32 + i) * 16 + w];

    int lane_sum = 0;
    #pragma unroll
    for (int i = 0; i < 32; i++) lane_sum += vals[i];

    int inc = lane_sum;
    #pragma unroll
    for (int d = 1; d < 32; d <<= 1) {
        int t = __shfl_up_sync(0xffffffffu, inc, d);
        if (lane >= d) inc += t;
    }
    int run = inc - lane_sum;

    #pragma unroll
    for (int i = 0; i < 32; i++) {
        int v = vals[i];
        g_blockcounts[(lane * 32 + i) * 16 + w] = run;   // within-rel base
        run += v;
    }
    if (lane == 31) rel_total[w] = run;
    __syncthreads();

    if (threadIdx.x == 0) {
        int tacc = 0;
        for (int r = 0; r < 16; r++) {
            tileofs_s[r] = tacc;
            g_relofs[r] = tacc * TILE;                   // padded base
            tacc += (rel_total[r] + TILE - 1) / TILE;
        }
        tileofs_s[16] = tacc;
        g_relofs[16] = tacc * TILE;
    }
    __syncthreads();

    int ntiles = tileofs_s[16];
    for (int t = threadIdx.x; t < MAXT; t += blockDim.x) {
        if (t < ntiles) {
            int r = 0;
            while (t >= tileofs_s[r + 1]) r++;
            g_tile_rel[t] = r;
        } else {
            g_tile_rel[t] = -1;
        }
    }

    // fill pad slots with (src=0, dst=-1): warp w pads relation w
    if (w < 16) {
        int start = g_relofs[w] + rel_total[w];
        int end   = g_relofs[w + 1];
        for (int p = start + lane; p < end; p += 32)
            g_edge[p] = make_int2(0, -1);
    }
}

// ---------------------------------------------------------------------------
// warp-aggregated counting-sort scatter
__global__ void k_scatter(const int* __restrict__ src, const int* __restrict__ dst,
                          const int* __restrict__ et, int E, int chunk) {
    __shared__ int cur[16];
    if (threadIdx.x < 16)
        cur[threadIdx.x] = g_relofs[threadIdx.x] +
                           g_blockcounts[blockIdx.x * 16 + threadIdx.x];
    __syncthreads();
    int lane = threadIdx.x & 31;
    int lo = blockIdx.x * chunk, hi = min(E, lo + chunk);
    for (int ebase = lo; ebase < hi; ebase += blockDim.x) {
        int e = ebase + threadIdx.x;
        bool valid = e < hi;
        unsigned act = __ballot_sync(0xffffffffu, valid);
        if (!valid) continue;
        int r = et[e];
        unsigned mask = __match_any_sync(act, r);
        int leader = __ffs(mask) - 1;
        int rank = __popc(mask & ((1u << lane) - 1));
        int base = 0;
        if (lane == leader) base = atomicAdd(&cur[r], __popc(mask));
        base = __shfl_sync(mask, base, leader);
        g_edge[base + rank] = make_int2(src[e], dst[e]);
    }
}

// ---------------------------------------------------------------------------
// fp16 m16n8k16 HMMA (sm_80+ portable)
#define MMA_F16(d, a, b)                                                      \
    asm volatile(                                                             \
        "mma.sync.aligned.m16n8k16.row.col.f32.f16.f16.f32 "                  \
        "{%0,%1,%2,%3}, {%4,%5,%6,%7}, {%8,%9}, {%0,%1,%2,%3};"               \
        : "+f"((d)[0]), "+f"((d)[1]), "+f"((d)[2]), "+f"((d)[3])              \
        : "r"((a)[0]), "r"((a)[1]), "r"((a)[2]), "r"((a)[3]),                 \
          "r"((b)[0]), "r"((b)[1]))

#define CPA16(saddr, gaddr)                                                   \
    asm volatile("cp.async.cg.shared.global [%0], [%1], 16;"                  \
                 :: "r"(saddr), "l"(gaddr))

// smem layout (bytes):
//   stage s (s=0,1) at s*16384: A 128 rows x 128 B, XOR-swizzled
//     (16B chunk ch of row r stored at r*128 + ((ch ^ (r&7))<<4))
//   Bh  at 32768 (64x72 halves = 9216, padded stride)
//   dsh at 41984 (2 stages x 128 int = 1024)
#define STAGE_BYTES 16384
#define SM_BHI  32768
#define SM_DST  41984
#define SMEM_DYN 43008
#define BSTRIDE 72           // halves per B row

__global__ __launch_bounds__(BLK, 5) void k_rgcn_mma(float* __restrict__ out) {
    extern __shared__ char smb[];
    unsigned short* Bh = (unsigned short*)(smb + SM_BHI);
    int* dsh = (int*)(smb + SM_DST);

    int tid = threadIdx.x, w = tid >> 5, lane = tid & 31;
    int g = lane >> 2, tig = lane & 3;

    uint32_t smbase;
    asm("{ .reg .u64 t; cvta.to.shared.u64 t, %1; cvt.u32.u64 %0, t; }"
        : "=r"(smbase) : "l"(smb));

    int per = (MAXT + GRID_MMA - 1) / GRID_MMA;
    int t0 = blockIdx.x * per, t1 = min(MAXT, t0 + per);
    int cur_rel = -1;

    // ---- prefetch tile tt into stage st (tile t = g_edge[128t..], padded,
    //      so no bounds logic). 8 lanes cooperate per feat row. ----
    int rsub = tid >> 3, ch = tid & 7;     // rsub: 0..15, ch: 0..7 (16B chunk)
    auto issue = [&](int tt, int st) {
        const int2* eb = g_edge + tt * TILE;
        #pragma unroll
        for (int it = 0; it < 8; it++) {
            int row = it * 16 + rsub;
            int2 e = eb[row];
            if (ch == 0) dsh[st * TILE + row] = e.y;
            uint32_t d = smbase + st * STAGE_BYTES + row * 128 +
                         ((ch ^ (row & 7)) << 4);
            CPA16(d, (const char*)g_fh + (size_t)e.x * 128 + ch * 16);
        }
    };

    // prologue: prefetch first tile into stage t0&1 (parity-correct)
    {
        if (t0 < t1 && g_tile_rel[t0] >= 0) issue(t0, t0 & 1);
        asm volatile("cp.async.commit_group;" ::: "memory");
    }

    for (int t = t0; t < t1; t++) {
        int rel = g_tile_rel[t];
        if (rel < 0) break;
        int st = t & 1;

        asm volatile("cp.async.wait_group 0;" ::: "memory");
        __syncthreads();   // stage st ready everywhere; all done with t-1

        // prefetch tile t+1 into the stage just vacated
        {
            int tn = t + 1;
            if (tn < t1 && g_tile_rel[tn] >= 0) issue(tn, tn & 1);
            asm volatile("cp.async.commit_group;" ::: "memory");
        }

        // B reload on relation change (rare: ~1-2 per CTA range)
        if (rel != cur_rel) {
            cur_rel = rel;
            #pragma unroll
            for (int c = 0; c < 4; c++) {
                int p8  = tid + c * BLK;            // 512 uint4 chunks
                int idx = p8 * 8;
                int nr = idx >> 6, k = idx & 63;
                *(uint4*)(Bh + nr * BSTRIDE + k) =
                    *(const uint4*)(g_Bh + rel * 4096 + idx);
            }
            __syncthreads();
        }

        const char* As = smb + st * STAGE_BYTES;
        const int* dshs = dsh + st * TILE;

        // GEMM: warp w owns rows [32w,32w+32) = 2 m16 x 8 n8 blocks, 1 pass
        float acc[2][8][4];
        #pragma unroll
        for (int m = 0; m < 2; m++)
            #pragma unroll
            for (int nb = 0; nb < 8; nb++)
                #pragma unroll
                for (int j = 0; j < 4; j++) acc[m][nb][j] = 0.f;

        #pragma unroll
        for (int ks = 0; ks < 4; ks++) {
            // A fragment: chunk = 2ks (+1), swizzle ^= (row&7) = g
            int c0 = ((2 * ks) ^ g) << 4, c1 = ((2 * ks + 1) ^ g) << 4;
            unsigned ah[2][4];
            #pragma unroll
            for (int m = 0; m < 2; m++) {
                const char* r0 = As + (32 * w + 16 * m + g) * 128 + tig * 4;
                const char* r1 = r0 + 8 * 128;
                ah[m][0] = *(const unsigned*)(r0 + c0);
                ah[m][1] = *(const unsigned*)(r1 + c0);
                ah[m][2] = *(const unsigned*)(r0 + c1);
                ah[m][3] = *(const unsigned*)(r1 + c1);
            }
            int kc = ks * 16 + 2 * tig;
            #pragma unroll
            for (int nb = 0; nb < 8; nb++) {
                int b0 = (8 * nb + g) * BSTRIDE + kc;
                unsigned bh[2];
                bh[0] = *(const unsigned*)(Bh + b0);
                bh[1] = *(const unsigned*)(Bh + b0 + 8);
                #pragma unroll
                for (int m = 0; m < 2; m++)
                    MMA_F16(acc[m][nb], ah[m], bh);
            }
        }

        // epilogue: partner-lane (lane^1) shfl -> red.v4, no smem staging
        #pragma unroll
        for (int m = 0; m < 2; m++) {
            int r0 = 32 * w + 16 * m + g;
            int dn0 = dshs[r0];
            int dn1 = dshs[r0 + 8];
            #pragma unroll
            for (int nb = 0; nb < 8; nb++) {
                float c0 = acc[m][nb][0], c1 = acc[m][nb][1];
                float c2 = acc[m][nb][2], c3 = acc[m][nb][3];
                float e0 = __shfl_xor_sync(0xffffffffu, c0, 1);
                float e1 = __shfl_xor_sync(0xffffffffu, c1, 1);
                float e2 = __shfl_xor_sync(0xffffffffu, c2, 1);
                float e3 = __shfl_xor_sync(0xffffffffu, c3, 1);
                if (tig & 1) {
                    if (dn1 >= 0) {
                        float* op = out + (long long)dn1 * 64 + 8 * nb + 2 * (tig - 1);
                        asm volatile("red.global.add.v4.f32 [%0], {%1, %2, %3, %4};"
                                     :: "l"(op), "f"(e2), "f"(e3), "f"(c2), "f"(c3)
                                     : "memory");
                    }
                } else {
                    if (dn0 >= 0) {
                        float* op = out + (long long)dn0 * 64 + 8 * nb + 2 * tig;
                        asm volatile("red.global.add.v4.f32 [%0], {%1, %2, %3, %4};"
                                     :: "l"(op), "f"(c0), "f"(c1), "f"(e0), "f"(e1)
                                     : "memory");
                    }
                }
            }
        }
        // no trailing barrier: next iteration's wait+syncthreads protects reuse
    }
}

// ---------------------------------------------------------------------------
extern "C" void kernel_launch(void* const* d_in, const int* in_sizes, int n_in,
                              void* d_out, int out_size) {
    const float* feat   = (const float*)d_in[0];   // [N, 64]
    const float* weight = (const float*)d_in[1];   // [16, 64, 64]
    const int*   src    = (const int*)d_in[2];     // [E]
    const int*   dst    = (const int*)d_in[3];     // [E]
    const int*   etyp   = (const int*)d_in[4];     // [E]
    float*       out    = (float*)d_out;           // [N, 64]

    int E = in_sizes[2];
    int n4 = out_size >> 2;
    int chunk = (E + NB_SORT - 1) / NB_SORT;

    cudaFuncSetAttribute(k_rgcn_mma, cudaFuncAttributeMaxDynamicSharedMemorySize,
                         SMEM_DYN);

    k_prep<<<NB_SORT, 256>>>((float4*)out, n4, weight, feat, etyp, E, chunk);
    k_scan<<<1, 512>>>();
    k_scatter<<<NB_SORT, 256>>>(src, dst, etyp, E, chunk);
    k_rgcn_mma<<<GRID_MMA, BLK, SMEM_DYN>>>(out);
}